// round 7
// baseline (speedup 1.0000x reference)
#include <cuda_runtime.h>
#include <cuda_bf16.h>

#define HH 1024
#define WW 1024
#define NB 8

typedef unsigned long long u64;

// ---- packed fp32x2 helpers (sm_103a FFMA2 path, PTX-only) ----
__device__ __forceinline__ u64 pk(float lo, float hi) {
    u64 r; asm("mov.b64 %0, {%1, %2};" : "=l"(r) : "f"(lo), "f"(hi)); return r;
}
__device__ __forceinline__ u64 fma2(u64 a, u64 b, u64 c) {
    u64 d; asm("fma.rn.f32x2 %0, %1, %2, %3;" : "=l"(d) : "l"(a), "l"(b), "l"(c));
    return d;
}

// Load the 6-wide window (cols w0-1 .. w0+4) of row hh: one aligned LDG.128 +
// two predicated edge scalars, all independent (preserve MLP — no shuffles).
__device__ __forceinline__ void load_row6(const float* __restrict__ base, int hh,
                                          int w0, float v[6]) {
    if (hh < 0 || hh >= HH) {
#pragma unroll
        for (int c = 0; c < 6; c++) v[c] = 0.0f;
        return;
    }
    const float* row = base + (size_t)hh * WW;
    float4 m = *reinterpret_cast<const float4*>(row + w0);
    v[1] = m.x; v[2] = m.y; v[3] = m.z; v[4] = m.w;
    v[0] = (w0 > 0) ? row[w0 - 1] : 0.0f;
    v[5] = (w0 + 4 < WW) ? row[w0 + 4] : 0.0f;
}

// 5 sliding f32x2 pairs from a 6-float window.
__device__ __forceinline__ void pack5(const float v[6], u64 p[5]) {
    p[0] = pk(v[0], v[1]);
    p[1] = pk(v[1], v[2]);
    p[2] = pk(v[2], v[3]);
    p[3] = pk(v[3], v[4]);
    p[4] = pk(v[4], v[5]);
}

__global__ void __launch_bounds__(128, 5)
small_sm_block_kernel(const float* __restrict__ image,
                      const float* __restrict__ x,
                      const float* __restrict__ wgt,   // (9,1,3,3) = 81
                      const float* __restrict__ bias,  // (9,)
                      float* __restrict__ y) {
    __shared__ u64 sw2[81];
    __shared__ u64 sb2[9];
    int t = threadIdx.x;
    if (t < 81) { float w = wgt[t];  sw2[t] = pk(w, w); }
    if (t < 9)  { float b = bias[t]; sb2[t] = pk(b, b); }
    __syncthreads();

    const int h0 = blockIdx.y * 2;                    // output rows h0, h0+1
    const int w0 = (blockIdx.x * blockDim.x + t) * 4; // 4 output cols

    // ---- K accumulators: packed over cols (01 / 23), rows A=h0, B=h0+1 ----
    u64 K01A[9], K23A[9], K01B[9], K23B[9];
#pragma unroll
    for (int j = 0; j < 9; j++) {
        u64 b2 = sb2[j];
        K01A[j] = b2; K23A[j] = b2; K01B[j] = b2; K23B[j] = b2;
    }

    // ---- K build: stream over tap-rows a; only rows a, a+1 packs resident.
    //      Each weight read exactly once (broadcast LDS.64). ----
    {
        float rf[6];
        u64 pa[5], pb[5];
        load_row6(image, h0 - 1, w0, rf); pack5(rf, pa);
        load_row6(image, h0,     w0, rf); pack5(rf, pb);
#pragma unroll
        for (int a = 0; a < 3; a++) {
            // prefetch next img row (for a+1 step) while computing
            float nf[6];
            if (a < 2) load_row6(image, h0 + 1 + a, w0, nf);
#pragma unroll
            for (int j = 0; j < 9; j++)
#pragma unroll
                for (int d = 0; d < 3; d++) {
                    u64 w2 = sw2[j * 9 + a * 3 + d];
                    K01A[j] = fma2(pa[d],     w2, K01A[j]);
                    K23A[j] = fma2(pa[d + 2], w2, K23A[j]);
                    K01B[j] = fma2(pb[d],     w2, K01B[j]);
                    K23B[j] = fma2(pb[d + 2], w2, K23B[j]);
                }
            if (a < 2) {
#pragma unroll
                for (int c = 0; c < 5; c++) pa[c] = pb[c];
                pack5(nf, pb);
            }
        }
    }

    // ---- apply: stream 4 x-rows per batch into 4 accumulator chains ----
    const size_t plane = (size_t)HH * WW;
    const size_t o0 = (size_t)h0 * WW + w0;
#pragma unroll
    for (int b = 0; b < NB; b++) {
        const float* xb = x + (size_t)b * plane;
        float xr0[6], xr1[6], xr2[6], xr3[6];
        load_row6(xb, h0 - 1, w0, xr0);
        load_row6(xb, h0,     w0, xr1);

        u64 a01A = 0ull, a23A = 0ull, a01B = 0ull, a23B = 0ull;
        u64 p[5];

        // row 0: A taps a=0
        pack5(xr0, p);
        load_row6(xb, h0 + 1, w0, xr2);
#pragma unroll
        for (int d = 0; d < 3; d++) {
            a01A = fma2(p[d],     K01A[d], a01A);
            a23A = fma2(p[d + 2], K23A[d], a23A);
        }

        // row 1: A taps a=1, B taps a=0
        pack5(xr1, p);
        load_row6(xb, h0 + 2, w0, xr3);
#pragma unroll
        for (int d = 0; d < 3; d++) {
            a01A = fma2(p[d],     K01A[3 + d], a01A);
            a23A = fma2(p[d + 2], K23A[3 + d], a23A);
            a01B = fma2(p[d],     K01B[d],     a01B);
            a23B = fma2(p[d + 2], K23B[d],     a23B);
        }

        // row 2: A taps a=2, B taps a=1
        pack5(xr2, p);
#pragma unroll
        for (int d = 0; d < 3; d++) {
            a01A = fma2(p[d],     K01A[6 + d], a01A);
            a23A = fma2(p[d + 2], K23A[6 + d], a23A);
            a01B = fma2(p[d],     K01B[3 + d], a01B);
            a23B = fma2(p[d + 2], K23B[3 + d], a23B);
        }

        // row 3: B taps a=2
        pack5(xr3, p);
#pragma unroll
        for (int d = 0; d < 3; d++) {
            a01B = fma2(p[d],     K01B[6 + d], a01B);
            a23B = fma2(p[d + 2], K23B[6 + d], a23B);
        }

        u64* yA = reinterpret_cast<u64*>(y + (size_t)b * plane + o0);
        u64* yB = reinterpret_cast<u64*>(y + (size_t)b * plane + o0 + WW);
        yA[0] = a01A; yA[1] = a23A;
        yB[0] = a01B; yB[1] = a23B;
    }
}

extern "C" void kernel_launch(void* const* d_in, const int* in_sizes, int n_in,
                              void* d_out, int out_size) {
    const float* image = (const float*)d_in[0];  // (1, 1024, 1024)
    const float* x     = (const float*)d_in[1];  // (8, 1, 1024, 1024)
    const float* klw   = (const float*)d_in[2];  // (9, 1, 3, 3)
    const float* klb   = (const float*)d_in[3];  // (9,)
    float* y = (float*)d_out;                    // (8, 1, 1024, 1024)

    dim3 block(128);
    dim3 grid(WW / 4 / 128, HH / 2);  // (2, 512)
    small_sm_block_kernel<<<grid, block>>>(image, x, klw, klb, y);
}